// round 1
// baseline (speedup 1.0000x reference)
#include <cuda_runtime.h>
#include <cstdint>

// AffinityLayer collapses algebraically:
//   out[b, p*20+x, q*20+y] = (x!=y && p!=q) ? P[x,p]+Q[x,q]+Q[y,p]+P[y,q] : 0
//                            + (p==q && x==y) ? Mn[x,p] : 0
// with per-batch 20x20 matrices:
//   P = F1 @ relu(L1) @ F2^T,  Q = F1 @ relu(L2) @ F2^T,  Mn = U1 @ U2^T
//
// One fused kernel: block = batch. Compute T1,T2 = F1 @ [relu(L1)|relu(L2)]
// with packed f32x2 FMAs, then P/Q/Mn dot products, then stream 640KB of
// output per batch (write-bound phase).

#define NB   256   // batches
#define NN   20    // nodes
#define DD   256   // internal dim
#define PSTR 21    // padded stride for 20x20 matrices (bank-conflict-free)

// shared layout (floats):
//   sA  [5120]  : transposed tile [d][20] (F1, then F2)
//   sT1 [5120]  : T1 transposed [e][20]
//   sT2 [5120]  : T2 transposed [e][20]
//   sP  [420], sQ [420], sMn [420]
#define OFF_A   0
#define OFF_T1  5120
#define OFF_T2  10240
#define OFF_P   15360
#define OFF_Q   15780
#define OFF_M   16200
#define SMEM_FLOATS 16620
#define SMEM_BYTES  (SMEM_FLOATS * 4)

__global__ void __launch_bounds__(256, 3)
affinity_kernel(const float* __restrict__ F1, const float* __restrict__ F2,
                const float* __restrict__ U1, const float* __restrict__ U2,
                const float* __restrict__ L1, const float* __restrict__ L2,
                float* __restrict__ out)
{
    extern __shared__ float sm[];
    float* sA  = sm + OFF_A;
    float* sT1 = sm + OFF_T1;
    float* sT2 = sm + OFF_T2;
    float* sP  = sm + OFF_P;
    float* sQ  = sm + OFF_Q;
    float* sMn = sm + OFF_M;

    const int b = blockIdx.x;
    const int t = threadIdx.x;

    // ---- 1. load F1 transposed: sA[d*20+i] = F1[b,i,d] ----
    {
        const float* f1 = F1 + (size_t)b * NN * DD;
        #pragma unroll
        for (int idx = t; idx < NN * DD; idx += 256) {
            int i = idx >> 8;      // 0..19
            int d = idx & 255;     // 0..255
            sA[d * NN + i] = f1[idx];
        }
    }
    __syncthreads();

    // ---- 2. T1[i,e] = sum_d F1[i,d]*relu(L1[d,e]) ; T2 with L2 ----
    // thread t = output column e. Accumulate 10 f32x2 pairs per weight.
    {
        const int e = t;
        const float* l1p = L1 + e;
        const float* l2p = L2 + e;
        unsigned long long a1[10], a2[10];
        #pragma unroll
        for (int j = 0; j < 10; j++) { a1[j] = 0ull; a2[j] = 0ull; }

        float w1r = l1p[0];
        float w2r = l2p[0];
        #pragma unroll 2
        for (int d = 0; d < DD; d++) {
            float w1 = fmaxf(w1r, 0.f);
            float w2 = fmaxf(w2r, 0.f);
            if (d < DD - 1) {           // prefetch next weight row (L2-resident)
                w1r = l1p[(d + 1) * DD];
                w2r = l2p[(d + 1) * DD];
            }
            unsigned long long ww1, ww2;
            asm("mov.b64 %0, {%1,%1};" : "=l"(ww1) : "r"(__float_as_uint(w1)));
            asm("mov.b64 %0, {%1,%1};" : "=l"(ww2) : "r"(__float_as_uint(w2)));
            const ulonglong2* row = reinterpret_cast<const ulonglong2*>(sA + d * NN);
            #pragma unroll
            for (int j = 0; j < 5; j++) {
                ulonglong2 fp = row[j];   // 4 consecutive F1[2j*2..], 16B aligned
                asm("fma.rn.f32x2 %0, %1, %2, %0;" : "+l"(a1[2*j  ]) : "l"(fp.x), "l"(ww1));
                asm("fma.rn.f32x2 %0, %1, %2, %0;" : "+l"(a1[2*j+1]) : "l"(fp.y), "l"(ww1));
                asm("fma.rn.f32x2 %0, %1, %2, %0;" : "+l"(a2[2*j  ]) : "l"(fp.x), "l"(ww2));
                asm("fma.rn.f32x2 %0, %1, %2, %0;" : "+l"(a2[2*j+1]) : "l"(fp.y), "l"(ww2));
            }
        }
        // write transposed: sT1[e*20 + i], as 5 float4 stores (16B aligned: e*80)
        #pragma unroll
        for (int j = 0; j < 5; j++) {
            uint32_t lo0, hi0, lo1, hi1;
            asm("mov.b64 {%0,%1}, %2;" : "=r"(lo0), "=r"(hi0) : "l"(a1[2*j]));
            asm("mov.b64 {%0,%1}, %2;" : "=r"(lo1), "=r"(hi1) : "l"(a1[2*j+1]));
            float4 v1 = make_float4(__uint_as_float(lo0), __uint_as_float(hi0),
                                    __uint_as_float(lo1), __uint_as_float(hi1));
            *reinterpret_cast<float4*>(sT1 + e * NN + 4 * j) = v1;
            asm("mov.b64 {%0,%1}, %2;" : "=r"(lo0), "=r"(hi0) : "l"(a2[2*j]));
            asm("mov.b64 {%0,%1}, %2;" : "=r"(lo1), "=r"(hi1) : "l"(a2[2*j+1]));
            float4 v2 = make_float4(__uint_as_float(lo0), __uint_as_float(hi0),
                                    __uint_as_float(lo1), __uint_as_float(hi1));
            *reinterpret_cast<float4*>(sT2 + e * NN + 4 * j) = v2;
        }
    }
    __syncthreads();

    // ---- 3. load F2 transposed into sA ----
    {
        const float* f2 = F2 + (size_t)b * NN * DD;
        #pragma unroll
        for (int idx = t; idx < NN * DD; idx += 256) {
            int k = idx >> 8;
            int d = idx & 255;
            sA[d * NN + k] = f2[idx];
        }
    }
    __syncthreads();

    // ---- 4. P[i,k] = sum_e T1[i,e]*F2[k,e] ; Q with T2 ----
    for (int idx = t; idx < NN * NN; idx += 256) {
        int i = idx / NN;
        int k = idx - i * NN;
        float accp = 0.f, accq = 0.f;
        #pragma unroll 4
        for (int e = 0; e < DD; e++) {
            float f  = sA [e * NN + k];
            accp = fmaf(sT1[e * NN + i], f, accp);
            accq = fmaf(sT2[e * NN + i], f, accq);
        }
        sP[i * PSTR + k] = accp;
        sQ[i * PSTR + k] = accq;
    }
    __syncthreads();

    // ---- 5. load U1,U2 transposed (reuse sT1,sT2) ----
    {
        const float* u1 = U1 + (size_t)b * NN * DD;
        const float* u2 = U2 + (size_t)b * NN * DD;
        #pragma unroll
        for (int idx = t; idx < NN * DD; idx += 256) {
            int i = idx >> 8;
            int d = idx & 255;
            sT1[d * NN + i] = u1[idx];
            sT2[d * NN + i] = u2[idx];
        }
    }
    __syncthreads();

    // ---- 6. Mn[i,k] = U1[i] . U2[k] ----
    for (int idx = t; idx < NN * NN; idx += 256) {
        int i = idx / NN;
        int k = idx - i * NN;
        float acc = 0.f;
        #pragma unroll 4
        for (int d = 0; d < DD; d++)
            acc = fmaf(sT1[d * NN + i], sT2[d * NN + k], acc);
        sMn[i * PSTR + k] = acc;
    }
    __syncthreads();

    // ---- 7. write phase: 160000 floats = 40000 float4 per batch ----
    // out[b, r=p*20+x, c=q*20+y]. Each float4 covers one q (20 % 4 == 0).
    {
        float4* ob = reinterpret_cast<float4*>(out + (size_t)b * 160000);
        for (int m = t; m < 40000; m += 256) {
            int r  = m / 100;          // row 0..399
            int cm = m - r * 100;      // float4 index within row, 0..99
            int p  = r / NN;
            int x  = r - p * NN;
            int q  = cm / 5;
            int y0 = (cm - q * 5) * 4; // starting y of this float4
            float4 v;
            float* vv = reinterpret_cast<float*>(&v);
            if (p != q) {
                float base = sP[x * PSTR + p] + sQ[x * PSTR + q];
                #pragma unroll
                for (int j = 0; j < 4; j++) {
                    int y = y0 + j;
                    vv[j] = (x != y) ? (base + sQ[y * PSTR + p] + sP[y * PSTR + q]) : 0.f;
                }
            } else {
                v = make_float4(0.f, 0.f, 0.f, 0.f);
                if (x >= y0 && x < y0 + 4)
                    vv[x - y0] = sMn[x * PSTR + p];   // diagonal node term
            }
            ob[m] = v;
        }
    }
}

extern "C" void kernel_launch(void* const* d_in, const int* in_sizes, int n_in,
                              void* d_out, int out_size)
{
    // Inputs (metadata order): F1,F2,U1,U2,G1,G2,H1,H2,mask,lambda1,lambda2.
    // Identify robustly by element count; relative order preserved.
    const float* Fs[4] = {nullptr, nullptr, nullptr, nullptr};
    const float* Ls[2] = {nullptr, nullptr};
    int nf = 0, nl = 0;
    for (int i = 0; i < n_in; i++) {
        if (in_sizes[i] == NB * NN * DD) {          // 1,310,720 : F1,F2,U1,U2
            if (nf < 4) Fs[nf++] = (const float*)d_in[i];
        } else if (in_sizes[i] == DD * DD) {        // 65,536 : lambda1, lambda2
            if (nl < 2) Ls[nl++] = (const float*)d_in[i];
        }
    }

    cudaFuncSetAttribute(affinity_kernel,
                         cudaFuncAttributeMaxDynamicSharedMemorySize, SMEM_BYTES);

    affinity_kernel<<<NB, 256, SMEM_BYTES>>>(Fs[0], Fs[1], Fs[2], Fs[3],
                                             Ls[0], Ls[1], (float*)d_out);
    (void)out_size;
}

// round 2
// speedup vs baseline: 1.2715x; 1.2715x over previous
#include <cuda_runtime.h>
#include <cstdint>

// out[b, p*20+x, q*20+y] = (x!=y && p!=q) ? P[x,p]+Q[x,q]+Q[y,p]+P[y,q] : 0
//                          + (p==q && x==y) ? Mn[x,p] : 0
// P = F1 @ relu(L1) @ F2^T, Q = F1 @ relu(L2) @ F2^T, Mn = U1 @ U2^T  (per batch, 20x20)
//
// Two kernels:
//   compute_kernel: grid (2, 256). block (m, b) computes P (m=0) or Q+Mn (m=1)
//                   into global scratch. Single wave, f32x2 FMA GEMM.
//   write_kernel:   grid (20, 256). block (p, b) streams 8000 floats of output.
//                   Full occupancy, write-bandwidth bound.

#define NB 256
#define NN 20
#define DD 256

__device__ float g_scratch[NB * 1200];   // per batch: P[400] | Q[400] | Mn[400]

// ---------------------------------------------------------------- compute ---
__global__ void __launch_bounds__(256, 4)
compute_kernel(const float* __restrict__ F1, const float* __restrict__ F2,
               const float* __restrict__ U1, const float* __restrict__ U2,
               const float* __restrict__ L1, const float* __restrict__ L2)
{
    extern __shared__ float sm[];
    float* sA = sm;          // 5120 floats: transposed [d][20] tile
    float* sT = sm + 5120;   // 5120 floats: T transposed [e][20]

    const int matId = blockIdx.x;   // 0 -> P via L1, 1 -> Q via L2 (+ Mn)
    const int b     = blockIdx.y;
    const int t     = threadIdx.x;

    // 1. load F1 transposed: sA[d*20+i] = F1[b,i,d]
    {
        const float* f1 = F1 + (size_t)b * NN * DD;
        #pragma unroll
        for (int idx = t; idx < NN * DD; idx += 256) {
            int i = idx >> 8, d = idx & 255;
            sA[d * NN + i] = f1[idx];
        }
    }
    __syncthreads();

    // 2. T[i,e] = sum_d F1[i,d] * relu(L[d,e]); thread t = column e.
    {
        const int e = t;
        const float* lp = (matId ? L2 : L1) + e;
        unsigned long long a[10];
        #pragma unroll
        for (int j = 0; j < 10; j++) a[j] = 0ull;

        float wr = lp[0];
        #pragma unroll 4
        for (int d = 0; d < DD; d++) {
            float w = fmaxf(wr, 0.f);
            if (d < DD - 1) wr = lp[(d + 1) * DD];   // prefetch (L2-resident)
            unsigned long long ww;
            asm("mov.b64 %0, {%1,%1};" : "=l"(ww) : "r"(__float_as_uint(w)));
            const ulonglong2* row = reinterpret_cast<const ulonglong2*>(sA + d * NN);
            #pragma unroll
            for (int j = 0; j < 5; j++) {
                ulonglong2 fp = row[j];
                asm("fma.rn.f32x2 %0, %1, %2, %0;" : "+l"(a[2*j  ]) : "l"(fp.x), "l"(ww));
                asm("fma.rn.f32x2 %0, %1, %2, %0;" : "+l"(a[2*j+1]) : "l"(fp.y), "l"(ww));
            }
        }
        // store transposed: sT[e*20 + i]
        #pragma unroll
        for (int j = 0; j < 5; j++) {
            uint32_t lo0, hi0, lo1, hi1;
            asm("mov.b64 {%0,%1}, %2;" : "=r"(lo0), "=r"(hi0) : "l"(a[2*j]));
            asm("mov.b64 {%0,%1}, %2;" : "=r"(lo1), "=r"(hi1) : "l"(a[2*j+1]));
            *reinterpret_cast<float4*>(sT + e * NN + 4 * j) =
                make_float4(__uint_as_float(lo0), __uint_as_float(hi0),
                            __uint_as_float(lo1), __uint_as_float(hi1));
        }
    }
    __syncthreads();

    // 3. load F2 transposed into sA (sA free after phase 2)
    {
        const float* f2 = F2 + (size_t)b * NN * DD;
        #pragma unroll
        for (int idx = t; idx < NN * DD; idx += 256) {
            int k = idx >> 8, d = idx & 255;
            sA[d * NN + k] = f2[idx];
        }
    }
    __syncthreads();

    // 4. P/Q[i,k] = sum_e T[i,e] * F2[k,e] -> scratch
    {
        float* dst = g_scratch + b * 1200 + matId * 400;
        for (int idx = t; idx < NN * NN; idx += 256) {
            int i = idx / NN, k = idx - i * NN;
            float a0 = 0.f, a1 = 0.f;
            #pragma unroll 4
            for (int e = 0; e < DD; e += 2) {
                a0 = fmaf(sT[ e      * NN + i], sA[ e      * NN + k], a0);
                a1 = fmaf(sT[(e + 1) * NN + i], sA[(e + 1) * NN + k], a1);
            }
            dst[idx] = a0 + a1;
        }
    }

    // 5. Mn[i,k] = U1[i] . U2[k]  (block matId==1 only; cheap)
    if (matId == 1) {
        __syncthreads();
        const float* u1 = U1 + (size_t)b * NN * DD;
        const float* u2 = U2 + (size_t)b * NN * DD;
        #pragma unroll
        for (int idx = t; idx < NN * DD; idx += 256) {
            int i = idx >> 8, d = idx & 255;
            sA[d * NN + i] = u1[idx];
            sT[d * NN + i] = u2[idx];
        }
        __syncthreads();
        float* dstm = g_scratch + b * 1200 + 800;
        for (int idx = t; idx < NN * NN; idx += 256) {
            int i = idx / NN, k = idx - i * NN;
            float a0 = 0.f, a1 = 0.f;
            #pragma unroll 4
            for (int d = 0; d < DD; d += 2) {
                a0 = fmaf(sA[ d      * NN + i], sT[ d      * NN + k], a0);
                a1 = fmaf(sA[(d + 1) * NN + i], sT[(d + 1) * NN + k], a1);
            }
            dstm[idx] = a0 + a1;
        }
    }
}

// ------------------------------------------------------------------ write ---
__global__ void __launch_bounds__(256, 8)
write_kernel(float* __restrict__ out)
{
    __shared__ __align__(16) float sPT[NN * 24];   // P transposed [q][y], stride 24
    __shared__ float sQs[NN * 21];                 // Q [x][q], stride 21
    __shared__ float sPcol[NN];                    // P[x][p]
    __shared__ __align__(16) float sQcol[NN];      // Q[y][p]
    __shared__ float sMncol[NN];                   // Mn[x][p]

    const int p = blockIdx.x;       // 0..19
    const int b = blockIdx.y;       // 0..255
    const int t = threadIdx.x;

    const float* Pb  = g_scratch + b * 1200;
    const float* Qb  = Pb + 400;
    const float* Mnb = Pb + 800;

    for (int idx = t; idx < 400; idx += 256) {
        int i = idx / NN, k = idx - i * NN;
        float pv = Pb[idx], qv = Qb[idx];
        sPT[k * 24 + i] = pv;
        sQs[i * 21 + k] = qv;
        if (k == p) { sPcol[i] = pv; sQcol[i] = qv; }
    }
    if (t < NN) sMncol[t] = Mnb[t * NN + p];
    __syncthreads();

    // rows r = p*20+x for x in [0,20); 100 float4 per row -> 2000 float4
    float4* ob = reinterpret_cast<float4*>(out) + (size_t)b * 40000 + p * 2000;
    #pragma unroll
    for (int it = 0; it < 8; it++) {
        int m = t + it * 256;
        if (m >= 2000) break;
        int x  = m / 100;
        int cm = m - x * 100;
        int q  = cm / 5;
        int y0 = (cm - q * 5) * 4;
        float4 v;
        if (q != p) {
            float  c1 = sPcol[x] + sQs[x * 21 + q];
            float4 pt = *reinterpret_cast<const float4*>(sPT + q * 24 + y0); // P[y][q]
            float4 qc = *reinterpret_cast<const float4*>(sQcol + y0);        // Q[y][p]
            v.x = c1 + pt.x + qc.x;
            v.y = c1 + pt.y + qc.y;
            v.z = c1 + pt.z + qc.z;
            v.w = c1 + pt.w + qc.w;
            int dx = x - y0;
            if ((unsigned)dx < 4u) reinterpret_cast<float*>(&v)[dx] = 0.f;   // x==y
        } else {
            v = make_float4(0.f, 0.f, 0.f, 0.f);
            int dx = x - y0;
            if ((unsigned)dx < 4u) reinterpret_cast<float*>(&v)[dx] = sMncol[x];
        }
        ob[m] = v;
    }
}

// ----------------------------------------------------------------- launch ---
extern "C" void kernel_launch(void* const* d_in, const int* in_sizes, int n_in,
                              void* d_out, int out_size)
{
    // Inputs (metadata order): F1,F2,U1,U2,G1,G2,H1,H2,mask,lambda1,lambda2.
    const float* Fs[4] = {nullptr, nullptr, nullptr, nullptr};
    const float* Ls[2] = {nullptr, nullptr};
    int nf = 0, nl = 0;
    for (int i = 0; i < n_in; i++) {
        if (in_sizes[i] == NB * NN * DD) {          // F1,F2,U1,U2
            if (nf < 4) Fs[nf++] = (const float*)d_in[i];
        } else if (in_sizes[i] == DD * DD) {        // lambda1, lambda2
            if (nl < 2) Ls[nl++] = (const float*)d_in[i];
        }
    }

    const int smemA = 10240 * sizeof(float);        // 40 KB
    cudaFuncSetAttribute(compute_kernel,
                         cudaFuncAttributeMaxDynamicSharedMemorySize, smemA);

    compute_kernel<<<dim3(2, NB), 256, smemA>>>(Fs[0], Fs[1], Fs[2], Fs[3],
                                                Ls[0], Ls[1]);
    write_kernel<<<dim3(NN, NB), 256>>>((float*)d_out);
    (void)out_size;
}

// round 3
// speedup vs baseline: 1.4064x; 1.1062x over previous
#include <cuda_runtime.h>
#include <cstdint>

// out[b, p*20+x, q*20+y] = (x!=y && p!=q) ? P[x,p]+Q[x,q]+Q[y,p]+P[y,q] : 0
//                          + (p==q && x==y) ? Mn[x,p] : 0
// P = F1 @ relu(L1) @ F2^T, Q = F1 @ relu(L2) @ F2^T, Mn = U1 @ U2^T (per batch)

#define NB 256
#define NN 20
#define DD 256
#define STRD 260   // row stride (floats) for [20][256] smem tiles; 16B-aligned rows

typedef unsigned long long ull;

__device__ float g_scratch[NB * 1200];   // per batch: P[400] | Q[400] | Mn[400]

#define FMA2(acc, x, y) \
    asm("fma.rn.f32x2 %0, %1, %2, %0;" : "+l"(acc) : "l"(x), "l"(y))

__device__ __forceinline__ float2 up64(ull v) {
    float2 r;
    asm("mov.b64 {%0,%1}, %2;" : "=f"(r.x), "=f"(r.y) : "l"(v));
    return r;
}

// ---------------------------------------------------------------- compute ---
__device__ __forceinline__ void pf8(float w[8], const float* lp, int c) {
    #pragma unroll
    for (int j = 0; j < 8; j++) w[j] = lp[(c * 8 + j) * DD];
}

__device__ __forceinline__ void comp8(ull a[10], const float w[8],
                                      const float* sA, int c) {
    #pragma unroll
    for (int j = 0; j < 8; j++) {
        float wr = fmaxf(w[j], 0.f);
        ull ww;
        asm("mov.b64 %0, {%1,%1};" : "=l"(ww) : "f"(wr));
        const ulonglong2* row =
            reinterpret_cast<const ulonglong2*>(sA + (c * 8 + j) * NN);
        #pragma unroll
        for (int v = 0; v < 5; v++) {
            ulonglong2 fp = row[v];
            FMA2(a[2 * v],     fp.x, ww);
            FMA2(a[2 * v + 1], fp.y, ww);
        }
    }
}

__global__ void __launch_bounds__(256, 3)
compute_kernel(const float* __restrict__ F1, const float* __restrict__ F2,
               const float* __restrict__ U1, const float* __restrict__ U2,
               const float* __restrict__ L1, const float* __restrict__ L2)
{
    __shared__ __align__(16) float sm[2 * NN * STRD];  // 10400 floats
    float* sR0 = sm;              // F1^T [d][20] -> F2 [k][STRD] -> U1 [i][STRD]
    float* sR1 = sm + NN * STRD;  // T [i][STRD]  -> U2 [k][STRD]

    const int matId = blockIdx.x;   // 0 -> P (L1), 1 -> Q (L2); Mn split by k
    const int b     = blockIdx.y;
    const int t     = threadIdx.x;

    // 1. F1 transposed: sR0[d*20+i] = F1[b,i,d]
    {
        const float* f1 = F1 + (size_t)b * NN * DD;
        #pragma unroll
        for (int idx = t; idx < NN * DD; idx += 256) {
            int i = idx >> 8, d = idx & 255;
            sR0[d * NN + i] = f1[idx];
        }
    }
    __syncthreads();

    // 2. T[i,e] = sum_d F1[i,d]*relu(L[d,e]); thread = column e.
    //    Depth-8 double-buffered weight prefetch (MLP=8, no serial chain).
    {
        const int e = t;
        const float* lp = (matId ? L2 : L1) + e;
        ull a[10];
        #pragma unroll
        for (int j = 0; j < 10; j++) a[j] = 0ull;

        float wA[8], wB[8];
        pf8(wA, lp, 0);
        pf8(wB, lp, 1);
        #pragma unroll 1
        for (int c = 0; c < 32; c += 2) {
            comp8(a, wA, sR0, c);
            if (c + 2 < 32) pf8(wA, lp, c + 2);
            comp8(a, wB, sR0, c + 1);
            if (c + 3 < 32) pf8(wB, lp, c + 3);
        }
        // store T row-major: sR1[i*STRD + e]
        #pragma unroll
        for (int v = 0; v < 10; v++) {
            float2 f = up64(a[v]);
            sR1[(2 * v)     * STRD + e] = f.x;
            sR1[(2 * v + 1) * STRD + e] = f.y;
        }
    }
    __syncthreads();

    // 3. F2 row-major into sR0: sR0[k*STRD + d]
    {
        const float4* f2v = reinterpret_cast<const float4*>(F2 + (size_t)b * NN * DD);
        #pragma unroll
        for (int i4 = t; i4 < NN * DD / 4; i4 += 256) {
            int k = i4 >> 6, d4 = i4 & 63;
            *reinterpret_cast<float4*>(sR0 + k * STRD + d4 * 4) = f2v[i4];
        }
    }
    __syncthreads();

    // 4. P/Q[i,k] = sum_e T[i,e]*F2[k,e] via LDS.128 + f32x2
    {
        float* dst = g_scratch + b * 1200 + matId * 400;
        for (int idx = t; idx < NN * NN; idx += 256) {
            int i = idx / NN, k = idx - i * NN;
            const ulonglong2* Ti = reinterpret_cast<const ulonglong2*>(sR1 + i * STRD);
            const ulonglong2* Fk = reinterpret_cast<const ulonglong2*>(sR0 + k * STRD);
            ull a0 = 0, a1 = 0, a2 = 0, a3 = 0;
            #pragma unroll
            for (int v = 0; v < DD / 4; v += 2) {
                ulonglong2 tv0 = Ti[v], tv1 = Ti[v + 1];
                ulonglong2 fv0 = Fk[v], fv1 = Fk[v + 1];
                FMA2(a0, tv0.x, fv0.x);
                FMA2(a1, tv0.y, fv0.y);
                FMA2(a2, tv1.x, fv1.x);
                FMA2(a3, tv1.y, fv1.y);
            }
            float2 s0 = up64(a0), s1 = up64(a1), s2 = up64(a2), s3 = up64(a3);
            dst[idx] = ((s0.x + s0.y) + (s1.x + s1.y)) +
                       ((s2.x + s2.y) + (s3.x + s3.y));
        }
    }
    __syncthreads();

    // 5. U1 -> sR0, U2 -> sR1, row-major
    {
        const float4* u1v = reinterpret_cast<const float4*>(U1 + (size_t)b * NN * DD);
        const float4* u2v = reinterpret_cast<const float4*>(U2 + (size_t)b * NN * DD);
        #pragma unroll
        for (int i4 = t; i4 < NN * DD / 4; i4 += 256) {
            int k = i4 >> 6, d4 = i4 & 63;
            *reinterpret_cast<float4*>(sR0 + k * STRD + d4 * 4) = u1v[i4];
            *reinterpret_cast<float4*>(sR1 + k * STRD + d4 * 4) = u2v[i4];
        }
    }
    __syncthreads();

    // 6. Mn[i,k] = U1[i].U2[k]; each matId block does its k half (balance).
    if (t < 200) {
        int i  = t / 10;
        int k  = matId * 10 + (t - i * 10);
        const ulonglong2* Ui = reinterpret_cast<const ulonglong2*>(sR0 + i * STRD);
        const ulonglong2* Uk = reinterpret_cast<const ulonglong2*>(sR1 + k * STRD);
        ull a0 = 0, a1 = 0, a2 = 0, a3 = 0;
        #pragma unroll
        for (int v = 0; v < DD / 4; v += 2) {
            ulonglong2 tv0 = Ui[v], tv1 = Ui[v + 1];
            ulonglong2 fv0 = Uk[v], fv1 = Uk[v + 1];
            FMA2(a0, tv0.x, fv0.x);
            FMA2(a1, tv0.y, fv0.y);
            FMA2(a2, tv1.x, fv1.x);
            FMA2(a3, tv1.y, fv1.y);
        }
        float2 s0 = up64(a0), s1 = up64(a1), s2 = up64(a2), s3 = up64(a3);
        g_scratch[b * 1200 + 800 + i * NN + k] =
            ((s0.x + s0.y) + (s1.x + s1.y)) + ((s2.x + s2.y) + (s3.x + s3.y));
    }
}

// ------------------------------------------------------------------ write ---
__global__ void __launch_bounds__(512)
write_kernel(float* __restrict__ out)
{
    __shared__ __align__(16) float sPT[NN * 24];   // P^T: [q][y], stride 24
    __shared__ float sQs[NN * 21];                 // Q: [x][q], stride 21
    __shared__ float sPcol[NN];                    // P[x][p]
    __shared__ __align__(16) float sQcol[NN];      // Q[y][p]
    __shared__ float sMn[NN];                      // Mn[x][p]

    const int p = blockIdx.x;
    const int b = blockIdx.y;
    const int t = threadIdx.x;

    const float* Pb = g_scratch + b * 1200;
    const float* Qb = Pb + 400;
    const float* Mb = Pb + 800;

    if (t < 400) {
        int i = t / NN, k = t - i * NN;
        float pv = Pb[t], qv = Qb[t];
        sPT[k * 24 + i] = pv;
        sQs[i * 21 + k] = qv;
        if (k == p) { sPcol[i] = pv; sQcol[i] = qv; }
    }
    if (t >= 480 && t < 500) sMn[t - 480] = Mb[(t - 480) * NN + p];
    __syncthreads();

    if (t < 500) {
        const int x0 = t / 100;
        const int cm = t - x0 * 100;          // float4 index within row
        const int q  = cm / 5;
        const int y0 = (cm - q * 5) * 4;

        float4* ob = reinterpret_cast<float4*>(out) +
                     (size_t)b * 40000 + p * 2000 + cm;

        if (q != p) {
            float4 pt = *reinterpret_cast<const float4*>(sPT + q * 24 + y0);
            float4 qc = *reinterpret_cast<const float4*>(sQcol + y0);
            const float bx = pt.x + qc.x, by = pt.y + qc.y;
            const float bz = pt.z + qc.z, bw = pt.w + qc.w;
            #pragma unroll
            for (int j = 0; j < 4; j++) {
                int x = x0 + 5 * j;
                float c1 = sPcol[x] + sQs[x * 21 + q];
                float4 v = make_float4(c1 + bx, c1 + by, c1 + bz, c1 + bw);
                int dx = x - y0;
                if (dx == 0) v.x = 0.f;
                else if (dx == 1) v.y = 0.f;
                else if (dx == 2) v.z = 0.f;
                else if (dx == 3) v.w = 0.f;
                ob[x * 100] = v;
            }
        } else {
            #pragma unroll
            for (int j = 0; j < 4; j++) {
                int x = x0 + 5 * j;
                float4 v = make_float4(0.f, 0.f, 0.f, 0.f);
                int dx = x - y0;
                if (dx == 0) v.x = sMn[x];
                else if (dx == 1) v.y = sMn[x];
                else if (dx == 2) v.z = sMn[x];
                else if (dx == 3) v.w = sMn[x];
                ob[x * 100] = v;
            }
        }
    }
}

// ----------------------------------------------------------------- launch ---
extern "C" void kernel_launch(void* const* d_in, const int* in_sizes, int n_in,
                              void* d_out, int out_size)
{
    // Inputs: F1,F2,U1,U2,G1,G2,H1,H2,mask,lambda1,lambda2 — pick by size.
    const float* Fs[4] = {nullptr, nullptr, nullptr, nullptr};
    const float* Ls[2] = {nullptr, nullptr};
    int nf = 0, nl = 0;
    for (int i = 0; i < n_in; i++) {
        if (in_sizes[i] == NB * NN * DD) {
            if (nf < 4) Fs[nf++] = (const float*)d_in[i];
        } else if (in_sizes[i] == DD * DD) {
            if (nl < 2) Ls[nl++] = (const float*)d_in[i];
        }
    }

    compute_kernel<<<dim3(2, NB), 256>>>(Fs[0], Fs[1], Fs[2], Fs[3], Ls[0], Ls[1]);
    write_kernel<<<dim3(NN, NB), 512>>>((float*)d_out);
    (void)out_size;
}